// round 9
// baseline (speedup 1.0000x reference)
#include <cuda_runtime.h>
#include <cstdint>

constexpr int NDRUG = 50000;
constexpr int NGENE = 50000;
constexpr int DHID  = 64;
constexpr int DEMB  = 32;
constexpr int EMAX  = 600000;

// Scratch (device globals — no allocation allowed)
__device__ float g_tm[2][NDRUG * 128];
__device__ float g_h[2][NDRUG * DHID];
__device__ float g_wt1[2][8 * 128 * 40];   // layer-1 weights, tf32 hi/lo split, tile-major
__device__ float g_wt2[2][4 * 64 * 40];    // layer-2 weights, split
__device__ int   g_deg[4 * NDRUG];
__device__ int   g_rowstart[4 * (NDRUG + 1)];
__device__ int   g_cursor[4 * (NDRUG + 1)];
__device__ int   g_csr[4 * EMAX];

struct Iptr4 { const int* p[4]; };
struct Ptr2  { const float* p[2]; };
struct Fptr2 { float* p[2]; };
struct PackAll {
    const float* w1[4];   // W1_dd, W1_dg, W1_gd, W1_gg
    const float* w2[4];
    float *wt1d, *wt1g, *wt2d, *wt2g;
};

// ---------------------------------------------------------------------------
// tf32 helpers
// ---------------------------------------------------------------------------
__device__ __forceinline__ float2 split_tf32(float v) {
    uint32_t hb;
    asm("cvt.rna.tf32.f32 %0, %1;" : "=r"(hb) : "f"(v));
    float hi = __uint_as_float(hb);
    float lo = v - hi;
    uint32_t lb;
    asm("cvt.rna.tf32.f32 %0, %1;" : "=r"(lb) : "f"(lo));
    return make_float2(hi, __uint_as_float(lb));
}

__device__ __forceinline__ void mma_tf32(float4& c, uint32_t a0, uint32_t a1,
                                         uint32_t a2, uint32_t a3,
                                         uint32_t b0, uint32_t b1) {
    asm volatile(
        "mma.sync.aligned.m16n8k8.row.col.f32.tf32.tf32.f32 "
        "{%0,%1,%2,%3}, {%4,%5,%6,%7}, {%8,%9}, {%0,%1,%2,%3};"
        : "+f"(c.x), "+f"(c.y), "+f"(c.z), "+f"(c.w)
        : "r"(a0), "r"(a1), "r"(a2), "r"(a3), "r"(b0), "r"(b1));
}

// ---------------------------------------------------------------------------
// prep: y<4 -> degree histogram (4 edges/thread); y==4 -> split-pack weights
// Packed weight layout per src type: [ktile][n][k16*2 + 8 pad] (40 floats/row),
// row = n, interleaved (hi,lo) pairs along k. Ready for contiguous smem copy.
// ---------------------------------------------------------------------------
__global__ void prep_kernel(Iptr4 dst, int* __restrict__ deg, int E,
                            int stride, PackAll pa) {
    int y = blockIdx.y;
    int idx = blockIdx.x * blockDim.x + threadIdx.x;
    if (y < 4) {
        const int* d = dst.p[y];
        int* dg = deg + y * NDRUG;
        int i0 = idx, i1 = idx + stride, i2 = idx + 2 * stride, i3 = idx + 3 * stride;
        if (i0 < E) atomicAdd(&dg[d[i0]], 1);
        if (i1 < E) atomicAdd(&dg[d[i1]], 1);
        if (i2 < E) atomicAdd(&dg[d[i2]], 1);
        if (i3 < E) atomicAdd(&dg[d[i3]], 1);
        return;
    }
    if (idx < 32768) {                       // layer 1: 2 src x 128 k x 128 n
        int src = idx >> 14;
        int j   = idx & 16383;
        int kg  = j >> 7;                    // 0..127
        int n   = j & 127;
        float v = (n < 64) ? pa.w1[src * 2][kg * 64 + n]
                           : pa.w1[src * 2 + 1][kg * 64 + n - 64];
        float2 s = split_tf32(v);
        float* dstp = (src ? pa.wt1g : pa.wt1d)
                    + (size_t)(kg / 16) * 128 * 40 + n * 40 + (kg % 16) * 2;
        dstp[0] = s.x; dstp[1] = s.y;
    } else if (idx < 40960) {                // layer 2: 2 src x 64 k x 64 n
        int j   = idx - 32768;
        int src = j >> 12;
        int jj  = j & 4095;
        int kg  = jj >> 6;                   // 0..63
        int n   = jj & 63;
        float v = (n < 32) ? pa.w2[src * 2][kg * 32 + n]
                           : pa.w2[src * 2 + 1][kg * 32 + n - 32];
        float2 s = split_tf32(v);
        float* dstp = (src ? pa.wt2g : pa.wt2d)
                    + (size_t)(kg / 16) * 64 * 40 + n * 40 + (kg % 16) * 2;
        dstp[0] = s.x; dstp[1] = s.y;
    }
}

// ---------------------------------------------------------------------------
// exclusive prefix scan of degrees -> rowstart AND cursor; 1 block/relation
// ---------------------------------------------------------------------------
__global__ __launch_bounds__(1024)
void scan4_kernel(const int* __restrict__ deg, int* __restrict__ rowstart,
                  int* __restrict__ cursor) {
    int r = blockIdx.x;
    const int* dg = deg + r * NDRUG;
    int* rs = rowstart + (size_t)r * (NDRUG + 1);
    int* cu = cursor   + (size_t)r * (NDRUG + 1);
    __shared__ int warpsum[32];
    __shared__ int carry_sh;
    int t = threadIdx.x, lane = t & 31, w = t >> 5;
    if (t == 0) carry_sh = 0;
    __syncthreads();
    for (int base = 0; base < NDRUG; base += 1024) {
        int idx = base + t;
        int v = (idx < NDRUG) ? dg[idx] : 0;
        int x = v;
#pragma unroll
        for (int off = 1; off < 32; off <<= 1) {
            int yv = __shfl_up_sync(~0u, x, off);
            if (lane >= off) x += yv;
        }
        if (lane == 31) warpsum[w] = x;
        __syncthreads();
        if (w == 0) {
            int s = warpsum[lane];
#pragma unroll
            for (int off = 1; off < 32; off <<= 1) {
                int yv = __shfl_up_sync(~0u, s, off);
                if (lane >= off) s += yv;
            }
            warpsum[lane] = s;
        }
        __syncthreads();
        int woff = (w > 0) ? warpsum[w - 1] : 0;
        int incl = x + woff;
        int carry = carry_sh;
        if (idx < NDRUG) { int val = carry + incl - v; rs[idx] = val; cu[idx] = val; }
        __syncthreads();
        if (t == 1023) carry_sh = carry + incl;
        __syncthreads();
    }
    if (t == 0) { rs[NDRUG] = carry_sh; cu[NDRUG] = carry_sh; }
}

// ---------------------------------------------------------------------------
// CSR fill: 4 independent edges per thread
// ---------------------------------------------------------------------------
__global__ void fill4_kernel(Iptr4 src, Iptr4 dst, int* __restrict__ cursor,
                             int* __restrict__ csr, int E, int stride) {
    int r = blockIdx.y;
    const int* s = src.p[r];
    const int* d = dst.p[r];
    int* cu = cursor + (size_t)r * (NDRUG + 1);
    int* cs = csr + (size_t)r * EMAX;
    int idx = blockIdx.x * blockDim.x + threadIdx.x;
    int i0 = idx, i1 = idx + stride, i2 = idx + 2 * stride, i3 = idx + 3 * stride;
    int d0 = (i0 < E) ? d[i0] : 0;
    int d1 = (i1 < E) ? d[i1] : 0;
    int d2 = (i2 < E) ? d[i2] : 0;
    int d3 = (i3 < E) ? d[i3] : 0;
    int p0 = (i0 < E) ? atomicAdd(&cu[d0], 1) : 0;
    int p1 = (i1 < E) ? atomicAdd(&cu[d1], 1) : 0;
    int p2 = (i2 < E) ? atomicAdd(&cu[d2], 1) : 0;
    int p3 = (i3 < E) ? atomicAdd(&cu[d3], 1) : 0;
    if (i0 < E) cs[p0] = s[i0];
    if (i1 < E) cs[p1] = s[i1];
    if (i2 < E) cs[p2] = s[i2];
    if (i3 < E) cs[p3] = s[i3];
}

// ---------------------------------------------------------------------------
// TF32 tensor-core GEMM (3xTF32): Y[y][M,N] = X[y][M,K] @ W[y][K,N]
// mma.sync.m16n8k8, block tile 128 x N, 8 warps. A split inline, W pre-split.
// smem rows: 16 k-values as interleaved (hi,lo) pairs + 8 pad = 40 floats.
// ---------------------------------------------------------------------------
template<int K, int N, int MW>
__global__ __launch_bounds__(256, 2)
void gemmt_kernel(Ptr2 Xa, Ptr2 Wta, Fptr2 Ya, int M) {
    constexpr int NW    = 8 / MW;
    constexpr int WarpM = 128 / MW;     // 32 (l1) / 16 (l2)
    constexpr int WarpN = N / NW;       // 64
    constexpr int MI    = WarpM / 16;   // 2 / 1
    constexpr int NJ    = WarpN / 8;    // 8
    constexpr int NT    = K / 16;

    const int y = blockIdx.y;
    const float* __restrict__ X  = Xa.p[y];
    const float* __restrict__ Wt = Wta.p[y];
    float* __restrict__ Y = Ya.p[y];

    __shared__ float As[128 * 40];
    __shared__ float Bs[N * 40];

    const int tid  = threadIdx.x;
    const int warp = tid >> 5, lane = tid & 31;
    const int wm = warp % MW, wn = warp / MW;
    const int m0 = blockIdx.x * 128;
    const int lr = lane >> 2;           // 0..7
    const int lc = lane & 3;            // 0..3

    float4 C[MI][NJ];
#pragma unroll
    for (int i = 0; i < MI; i++)
#pragma unroll
        for (int j = 0; j < NJ; j++) C[i][j] = make_float4(0.f, 0.f, 0.f, 0.f);

    for (int t = 0; t < NT; t++) {
        // --- A stage: 128 rows x 16 k, split to (hi,lo) interleaved ---
#pragma unroll
        for (int it = 0; it < 2; it++) {
            int lin = tid + it * 256;        // 0..511 float4
            int m = lin >> 2, kq = lin & 3;
            int gr = m0 + m;
            float4 v = make_float4(0.f, 0.f, 0.f, 0.f);
            if (gr < M) v = *(const float4*)(X + (size_t)gr * K + t * 16 + kq * 4);
            float2 s0 = split_tf32(v.x), s1 = split_tf32(v.y);
            float2 s2 = split_tf32(v.z), s3 = split_tf32(v.w);
            float* p = As + m * 40 + kq * 8;
            *(float4*)p       = make_float4(s0.x, s0.y, s1.x, s1.y);
            *(float4*)(p + 4) = make_float4(s2.x, s2.y, s3.x, s3.y);
        }
        // --- B stage: contiguous copy of pre-split weight tile ---
        {
            const float4* wt4 = (const float4*)(Wt + (size_t)t * N * 40);
            float4* bs4 = (float4*)Bs;
            for (int i = tid; i < N * 10; i += 256) bs4[i] = wt4[i];
        }
        __syncthreads();
#pragma unroll
        for (int k8 = 0; k8 < 2; k8++) {
            const int kb = k8 * 8;
            float2 a[MI][4];
#pragma unroll
            for (int i = 0; i < MI; i++) {
                int ml = wm * WarpM + i * 16 + lr;
                a[i][0] = *(const float2*)(As + ml * 40 + (kb + lc) * 2);
                a[i][1] = *(const float2*)(As + (ml + 8) * 40 + (kb + lc) * 2);
                a[i][2] = *(const float2*)(As + ml * 40 + (kb + lc + 4) * 2);
                a[i][3] = *(const float2*)(As + (ml + 8) * 40 + (kb + lc + 4) * 2);
            }
#pragma unroll
            for (int j = 0; j < NJ; j++) {
                int nl = wn * WarpN + j * 8 + lr;
                float2 b0 = *(const float2*)(Bs + nl * 40 + (kb + lc) * 2);
                float2 b1 = *(const float2*)(Bs + nl * 40 + (kb + lc + 4) * 2);
#pragma unroll
                for (int i = 0; i < MI; i++) {
                    uint32_t ah0 = __float_as_uint(a[i][0].x), ah1 = __float_as_uint(a[i][1].x);
                    uint32_t ah2 = __float_as_uint(a[i][2].x), ah3 = __float_as_uint(a[i][3].x);
                    uint32_t al0 = __float_as_uint(a[i][0].y), al1 = __float_as_uint(a[i][1].y);
                    uint32_t al2 = __float_as_uint(a[i][2].y), al3 = __float_as_uint(a[i][3].y);
                    uint32_t bh0 = __float_as_uint(b0.x), bh1 = __float_as_uint(b1.x);
                    uint32_t bl0 = __float_as_uint(b0.y), bl1 = __float_as_uint(b1.y);
                    mma_tf32(C[i][j], ah0, ah1, ah2, ah3, bh0, bh1);   // hi*hi
                    mma_tf32(C[i][j], al0, al1, al2, al3, bh0, bh1);   // lo*hi
                    mma_tf32(C[i][j], ah0, ah1, ah2, ah3, bl0, bl1);   // hi*lo
                }
            }
        }
        __syncthreads();
    }
    // --- store ---
#pragma unroll
    for (int i = 0; i < MI; i++) {
        int r0 = m0 + wm * WarpM + i * 16 + lr;
#pragma unroll
        for (int j = 0; j < NJ; j++) {
            int col = wn * WarpN + j * 8 + lc * 2;
            if (r0 < M)
                *(float2*)(Y + (size_t)r0 * N + col) = make_float2(C[i][j].x, C[i][j].y);
            if (r0 + 8 < M)
                *(float2*)(Y + (size_t)(r0 + 8) * N + col) = make_float2(C[i][j].z, C[i][j].w);
        }
    }
}

// ---------------------------------------------------------------------------
// Fused dual gather (multi-edge-per-warp, LDG.128)
// ---------------------------------------------------------------------------
struct GatherCfg {
    const float* tmA; const int* csrA; const int* rsA;
    const float* tmB; const int* csrB; const int* rsB;
    const float* bias; float* out;
};

template<int D, int LD, bool RELU>
__launch_bounds__(256)
__global__ void gather_dual_kernel(GatherCfg c0, GatherCfg c1, int n) {
    constexpr int LANES  = D / 4;
    constexpr int GROUPS = 32 / LANES;
    const GatherCfg c = blockIdx.y ? c1 : c0;
    int warp = (blockIdx.x * blockDim.x + threadIdx.x) >> 5;
    int lane = threadIdx.x & 31;
    if (warp >= n) return;
    int grp = lane / LANES;
    int h   = lane % LANES;

    float4 res = *(const float4*)(c.bias + h * 4);

#pragma unroll
    for (int rel = 0; rel < 2; rel++) {
        const float* __restrict__ tm  = rel ? c.tmB  : c.tmA;
        const int*   __restrict__ csr = rel ? c.csrB : c.csrA;
        const int*   __restrict__ rs  = rel ? c.rsB  : c.rsA;
        int s = rs[warp], e = rs[warp + 1];
        float inv = 1.0f / (float)max(e - s, 1);
        float4 acc = make_float4(0.f, 0.f, 0.f, 0.f);
        int i = s + grp;
        for (; i + GROUPS < e; i += 2 * GROUPS) {
            int r0 = csr[i];
            int r1 = csr[i + GROUPS];
            float4 v0 = *(const float4*)(tm + (size_t)r0 * LD + h * 4);
            float4 v1 = *(const float4*)(tm + (size_t)r1 * LD + h * 4);
            acc.x += v0.x + v1.x; acc.y += v0.y + v1.y;
            acc.z += v0.z + v1.z; acc.w += v0.w + v1.w;
        }
        if (i < e) {
            int r0 = csr[i];
            float4 v0 = *(const float4*)(tm + (size_t)r0 * LD + h * 4);
            acc.x += v0.x; acc.y += v0.y; acc.z += v0.z; acc.w += v0.w;
        }
#pragma unroll
        for (int off = LANES; off < 32; off <<= 1) {
            acc.x += __shfl_xor_sync(~0u, acc.x, off);
            acc.y += __shfl_xor_sync(~0u, acc.y, off);
            acc.z += __shfl_xor_sync(~0u, acc.z, off);
            acc.w += __shfl_xor_sync(~0u, acc.w, off);
        }
        res.x += acc.x * inv; res.y += acc.y * inv;
        res.z += acc.z * inv; res.w += acc.w * inv;
    }

    if (RELU) {
        res.x = fmaxf(res.x, 0.f); res.y = fmaxf(res.y, 0.f);
        res.z = fmaxf(res.z, 0.f); res.w = fmaxf(res.w, 0.f);
    }
    if (grp == 0)
        ((float4*)(c.out + (size_t)warp * D))[h] = res;
}

// ---------------------------------------------------------------------------
// Orchestration
// ---------------------------------------------------------------------------
extern "C" void kernel_launch(void* const* d_in, const int* in_sizes, int n_in,
                              void* d_out, int out_size) {
    const float* xd = (const float*)d_in[0];
    const float* xg = (const float*)d_in[1];
    const int* es[8];
    for (int i = 0; i < 8; i++) es[i] = (const int*)d_in[2 + i];
    const float* W1[4] = {(const float*)d_in[10], (const float*)d_in[11],
                          (const float*)d_in[12], (const float*)d_in[13]};
    const float* b1d = (const float*)d_in[14];
    const float* b1g = (const float*)d_in[15];
    const float* W2[4] = {(const float*)d_in[16], (const float*)d_in[17],
                          (const float*)d_in[18], (const float*)d_in[19]};
    const float* b2d = (const float*)d_in[20];
    const float* b2g = (const float*)d_in[21];
    float* out = (float*)d_out;
    const int E = in_sizes[2];

    float *tm, *h, *wt1, *wt2;
    int *deg, *rowstart, *cursor, *csr;
    cudaGetSymbolAddress((void**)&tm,       g_tm);
    cudaGetSymbolAddress((void**)&h,        g_h);
    cudaGetSymbolAddress((void**)&wt1,      g_wt1);
    cudaGetSymbolAddress((void**)&wt2,      g_wt2);
    cudaGetSymbolAddress((void**)&deg,      g_deg);
    cudaGetSymbolAddress((void**)&rowstart, g_rowstart);
    cudaGetSymbolAddress((void**)&cursor,   g_cursor);
    cudaGetSymbolAddress((void**)&csr,      g_csr);

    const int TB = 256;
    const int gblk = (NDRUG + 127) / 128;                 // 391
    const int eblk4 = (E + TB * 4 - 1) / (TB * 4);
    const int estride = eblk4 * TB;

    Iptr4 srcs = {{es[0], es[2], es[4], es[6]}};
    Iptr4 dsts = {{es[1], es[3], es[5], es[7]}};

    float* tm0 = tm;
    float* tm1 = tm + (size_t)NDRUG * 128;
    float* wt1d = wt1;                 float* wt1g = wt1 + 8 * 128 * 40;
    float* wt2d = wt2;                 float* wt2g = wt2 + 4 * 64 * 40;

    // --- prep: degrees + tf32 split-pack of weights ---
    cudaMemsetAsync(deg, 0, sizeof(int) * 4 * NDRUG, 0);
    PackAll pa;
    for (int i = 0; i < 4; i++) { pa.w1[i] = W1[i]; pa.w2[i] = W2[i]; }
    pa.wt1d = wt1d; pa.wt1g = wt1g; pa.wt2d = wt2d; pa.wt2g = wt2g;
    prep_kernel<<<dim3(eblk4, 5), TB>>>(dsts, deg, E, estride, pa);

    // --- scan (writes rowstart + cursor) ---
    scan4_kernel<<<4, 1024>>>(deg, rowstart, cursor);

    // --- CSR fill ---
    fill4_kernel<<<dim3(eblk4, 4), TB>>>(srcs, dsts, cursor, csr, E, estride);

    const int* rs[4] = {rowstart, rowstart + (NDRUG + 1),
                        rowstart + 2 * (NDRUG + 1), rowstart + 3 * (NDRUG + 1)};
    const int* cs[4] = {csr, csr + EMAX, csr + 2 * (size_t)EMAX, csr + 3 * (size_t)EMAX};

    int gather_blocks = (NDRUG * 32 + TB - 1) / TB;

    // --- layer 1: tf32 tensor GEMM + fused gather ---
    {
        Ptr2  X = {{xd, xg}};
        Ptr2  W = {{wt1d, wt1g}};
        Fptr2 Y = {{tm0, tm1}};
        gemmt_kernel<128, 128, 4><<<dim3(gblk, 2), 256>>>(X, W, Y, NDRUG);

        GatherCfg cd = {tm0,      cs[0], rs[0], tm1,      cs[2], rs[2], b1d, h};
        GatherCfg cg = {tm0 + 64, cs[1], rs[1], tm1 + 64, cs[3], rs[3], b1g,
                        h + (size_t)NDRUG * DHID};
        gather_dual_kernel<64, 128, true><<<dim3(gather_blocks, 2), TB>>>(cd, cg, NDRUG);
    }

    // --- layer 2 ---
    {
        const float* hd = h;
        const float* hg = h + (size_t)NDRUG * DHID;
        Ptr2  X = {{hd, hg}};
        Ptr2  W = {{wt2d, wt2g}};
        Fptr2 Y = {{tm0, tm1}};
        gemmt_kernel<64, 64, 8><<<dim3(gblk, 2), 256>>>(X, W, Y, NDRUG);

        GatherCfg cd = {tm0,      cs[0], rs[0], tm1,      cs[2], rs[2], b2d, out};
        GatherCfg cg = {tm0 + 32, cs[1], rs[1], tm1 + 32, cs[3], rs[3], b2g,
                        out + (size_t)NDRUG * DEMB};
        gather_dual_kernel<32, 64, false><<<dim3(gather_blocks, 2), TB>>>(cd, cg, NDRUG);
    }
}

// round 13
// speedup vs baseline: 1.1166x; 1.1166x over previous
#include <cuda_runtime.h>
#include <cuda_pipeline.h>
#include <cstdint>

constexpr int NDRUG = 50000;
constexpr int NGENE = 50000;
constexpr int DHID  = 64;
constexpr int DEMB  = 32;
constexpr int EMAX  = 600000;

// Scratch (device globals — no allocation allowed)
__device__ float g_tm[2][NDRUG * 128];
__device__ float g_h[2][NDRUG * DHID];
__device__ float g_wt1[2][8 * 128 * 40];   // layer-1 weights, tf32 hi/lo split, tile-major
__device__ float g_wt2[2][4 * 64 * 40];    // layer-2 weights, split
__device__ int   g_deg[4 * NDRUG];
__device__ int   g_rowstart[4 * (NDRUG + 1)];
__device__ int   g_cursor[4 * (NDRUG + 1)];
__device__ int   g_csr[4 * EMAX];

struct Iptr4 { const int* p[4]; };
struct Ptr2  { const float* p[2]; };
struct Fptr2 { float* p[2]; };
struct PackAll {
    const float* w1[4];
    const float* w2[4];
    float *wt1d, *wt1g, *wt2d, *wt2g;
};

// ---------------------------------------------------------------------------
// tf32 helpers
// ---------------------------------------------------------------------------
__device__ __forceinline__ float2 split_tf32(float v) {
    uint32_t hb;
    asm("cvt.rna.tf32.f32 %0, %1;" : "=r"(hb) : "f"(v));
    float hi = __uint_as_float(hb);
    float lo = v - hi;
    uint32_t lb;
    asm("cvt.rna.tf32.f32 %0, %1;" : "=r"(lb) : "f"(lo));
    return make_float2(hi, __uint_as_float(lb));
}

__device__ __forceinline__ void mma_tf32(float4& c, uint32_t a0, uint32_t a1,
                                         uint32_t a2, uint32_t a3,
                                         uint32_t b0, uint32_t b1) {
    asm volatile(
        "mma.sync.aligned.m16n8k8.row.col.f32.tf32.tf32.f32 "
        "{%0,%1,%2,%3}, {%4,%5,%6,%7}, {%8,%9}, {%0,%1,%2,%3};"
        : "+f"(c.x), "+f"(c.y), "+f"(c.z), "+f"(c.w)
        : "r"(a0), "r"(a1), "r"(a2), "r"(a3), "r"(b0), "r"(b1));
}

// ---------------------------------------------------------------------------
// prep: y<4 -> degree histogram (4 edges/thread); y==4 -> split-pack weights
// ---------------------------------------------------------------------------
__global__ void prep_kernel(Iptr4 dst, int* __restrict__ deg, int E,
                            int stride, PackAll pa) {
    int y = blockIdx.y;
    int idx = blockIdx.x * blockDim.x + threadIdx.x;
    if (y < 4) {
        const int* d = dst.p[y];
        int* dg = deg + y * NDRUG;
        int i0 = idx, i1 = idx + stride, i2 = idx + 2 * stride, i3 = idx + 3 * stride;
        if (i0 < E) atomicAdd(&dg[d[i0]], 1);
        if (i1 < E) atomicAdd(&dg[d[i1]], 1);
        if (i2 < E) atomicAdd(&dg[d[i2]], 1);
        if (i3 < E) atomicAdd(&dg[d[i3]], 1);
        return;
    }
    if (idx < 32768) {                       // layer 1: 2 src x 128 k x 128 n
        int src = idx >> 14;
        int j   = idx & 16383;
        int kg  = j >> 7;
        int n   = j & 127;
        float v = (n < 64) ? pa.w1[src * 2][kg * 64 + n]
                           : pa.w1[src * 2 + 1][kg * 64 + n - 64];
        float2 s = split_tf32(v);
        float* dstp = (src ? pa.wt1g : pa.wt1d)
                    + (size_t)(kg / 16) * 128 * 40 + n * 40 + (kg % 16) * 2;
        dstp[0] = s.x; dstp[1] = s.y;
    } else if (idx < 40960) {                // layer 2: 2 src x 64 k x 64 n
        int j   = idx - 32768;
        int src = j >> 12;
        int jj  = j & 4095;
        int kg  = jj >> 6;
        int n   = jj & 63;
        float v = (n < 32) ? pa.w2[src * 2][kg * 32 + n]
                           : pa.w2[src * 2 + 1][kg * 32 + n - 32];
        float2 s = split_tf32(v);
        float* dstp = (src ? pa.wt2g : pa.wt2d)
                    + (size_t)(kg / 16) * 64 * 40 + n * 40 + (kg % 16) * 2;
        dstp[0] = s.x; dstp[1] = s.y;
    }
}

// ---------------------------------------------------------------------------
// exclusive prefix scan of degrees -> rowstart AND cursor; 1 block/relation
// ---------------------------------------------------------------------------
__global__ __launch_bounds__(1024)
void scan4_kernel(const int* __restrict__ deg, int* __restrict__ rowstart,
                  int* __restrict__ cursor) {
    int r = blockIdx.x;
    const int* dg = deg + r * NDRUG;
    int* rs = rowstart + (size_t)r * (NDRUG + 1);
    int* cu = cursor   + (size_t)r * (NDRUG + 1);
    __shared__ int warpsum[32];
    __shared__ int carry_sh;
    int t = threadIdx.x, lane = t & 31, w = t >> 5;
    if (t == 0) carry_sh = 0;
    __syncthreads();
    for (int base = 0; base < NDRUG; base += 1024) {
        int idx = base + t;
        int v = (idx < NDRUG) ? dg[idx] : 0;
        int x = v;
#pragma unroll
        for (int off = 1; off < 32; off <<= 1) {
            int yv = __shfl_up_sync(~0u, x, off);
            if (lane >= off) x += yv;
        }
        if (lane == 31) warpsum[w] = x;
        __syncthreads();
        if (w == 0) {
            int s = warpsum[lane];
#pragma unroll
            for (int off = 1; off < 32; off <<= 1) {
                int yv = __shfl_up_sync(~0u, s, off);
                if (lane >= off) s += yv;
            }
            warpsum[lane] = s;
        }
        __syncthreads();
        int woff = (w > 0) ? warpsum[w - 1] : 0;
        int incl = x + woff;
        int carry = carry_sh;
        if (idx < NDRUG) { int val = carry + incl - v; rs[idx] = val; cu[idx] = val; }
        __syncthreads();
        if (t == 1023) carry_sh = carry + incl;
        __syncthreads();
    }
    if (t == 0) { rs[NDRUG] = carry_sh; cu[NDRUG] = carry_sh; }
}

// ---------------------------------------------------------------------------
// CSR fill: 4 independent edges per thread
// ---------------------------------------------------------------------------
__global__ void fill4_kernel(Iptr4 src, Iptr4 dst, int* __restrict__ cursor,
                             int* __restrict__ csr, int E, int stride) {
    int r = blockIdx.y;
    const int* s = src.p[r];
    const int* d = dst.p[r];
    int* cu = cursor + (size_t)r * (NDRUG + 1);
    int* cs = csr + (size_t)r * EMAX;
    int idx = blockIdx.x * blockDim.x + threadIdx.x;
    int i0 = idx, i1 = idx + stride, i2 = idx + 2 * stride, i3 = idx + 3 * stride;
    int d0 = (i0 < E) ? d[i0] : 0;
    int d1 = (i1 < E) ? d[i1] : 0;
    int d2 = (i2 < E) ? d[i2] : 0;
    int d3 = (i3 < E) ? d[i3] : 0;
    int p0 = (i0 < E) ? atomicAdd(&cu[d0], 1) : 0;
    int p1 = (i1 < E) ? atomicAdd(&cu[d1], 1) : 0;
    int p2 = (i2 < E) ? atomicAdd(&cu[d2], 1) : 0;
    int p3 = (i3 < E) ? atomicAdd(&cu[d3], 1) : 0;
    if (i0 < E) cs[p0] = s[i0];
    if (i1 < E) cs[p1] = s[i1];
    if (i2 < E) cs[p2] = s[i2];
    if (i3 < E) cs[p3] = s[i3];
}

// ---------------------------------------------------------------------------
// Pipelined TF32 tensor-core GEMM (3xTF32): Y[y][M,N] = X[y][M,K] @ W[y][K,N]
// Double-buffered dynamic smem; B via cp.async; A via register prefetch.
// smem rows: 16 k-values as interleaved (hi,lo) pairs + 8 pad = 40 floats.
// ---------------------------------------------------------------------------
template<int K, int N, int MW>
__global__ __launch_bounds__(256, 2)
void gemmt_kernel(Ptr2 Xa, Ptr2 Wta, Fptr2 Ya, int M) {
    constexpr int NW    = 8 / MW;
    constexpr int WarpM = 128 / MW;
    constexpr int WarpN = N / NW;
    constexpr int MI    = WarpM / 16;
    constexpr int NJ    = WarpN / 8;
    constexpr int NT    = K / 16;
    constexpr int ASZ   = 128 * 40;       // floats per A buffer
    constexpr int BSZ   = N * 40;         // floats per B buffer

    const int y = blockIdx.y;
    const float* __restrict__ X  = Xa.p[y];
    const float* __restrict__ Wt = Wta.p[y];
    float* __restrict__ Y = Ya.p[y];

    extern __shared__ float sm[];
    float* Asb = sm;                      // [2][ASZ]
    float* Bsb = sm + 2 * ASZ;            // [2][BSZ]

    const int tid  = threadIdx.x;
    const int warp = tid >> 5, lane = tid & 31;
    const int wm = warp % MW, wn = warp / MW;
    const int m0 = blockIdx.x * 128;
    const int lr = lane >> 2;
    const int lc = lane & 3;

    float4 C[MI][NJ];
#pragma unroll
    for (int i = 0; i < MI; i++)
#pragma unroll
        for (int j = 0; j < NJ; j++) C[i][j] = make_float4(0.f, 0.f, 0.f, 0.f);

    float4 xv[2];
    // precomputed per-thread stage coords: lin = tid + it*256 -> m, kq
    // (m = lin>>2, kq = lin&3)

    // ---- prologue: tile 0 ----
#pragma unroll
    for (int it = 0; it < 2; it++) {
        int lin = tid + it * 256;
        int m = lin >> 2, kq = lin & 3;
        int gr = m0 + m;
        xv[it] = make_float4(0.f, 0.f, 0.f, 0.f);
        if (gr < M) xv[it] = *(const float4*)(X + (size_t)gr * K + kq * 4);
    }
#pragma unroll
    for (int it = 0; it < 2; it++) {
        int lin = tid + it * 256;
        int m = lin >> 2, kq = lin & 3;
        float2 s0 = split_tf32(xv[it].x), s1 = split_tf32(xv[it].y);
        float2 s2 = split_tf32(xv[it].z), s3 = split_tf32(xv[it].w);
        float* p = Asb + m * 40 + kq * 8;
        *(float4*)p       = make_float4(s0.x, s0.y, s1.x, s1.y);
        *(float4*)(p + 4) = make_float4(s2.x, s2.y, s3.x, s3.y);
    }
    {
        const float4* src = (const float4*)Wt;
        float4* dst = (float4*)Bsb;
        for (int i = tid; i < BSZ / 4; i += 256)
            __pipeline_memcpy_async(dst + i, src + i, 16);
    }
    __pipeline_commit();

    for (int t = 0; t < NT; t++) {
        const int buf  = t & 1;
        const int nbuf = buf ^ 1;
        const bool more = (t + 1 < NT);

        if (more) {
            // prefetch X tile t+1 into registers
#pragma unroll
            for (int it = 0; it < 2; it++) {
                int lin = tid + it * 256;
                int m = lin >> 2, kq = lin & 3;
                int gr = m0 + m;
                xv[it] = make_float4(0.f, 0.f, 0.f, 0.f);
                if (gr < M)
                    xv[it] = *(const float4*)(X + (size_t)gr * K + (t + 1) * 16 + kq * 4);
            }
            // async B tile t+1
            const float4* src = (const float4*)(Wt + (size_t)(t + 1) * BSZ);
            float4* dst = (float4*)(Bsb + nbuf * BSZ);
            for (int i = tid; i < BSZ / 4; i += 256)
                __pipeline_memcpy_async(dst + i, src + i, 16);
            __pipeline_commit();
            __pipeline_wait_prior(1);
        } else {
            __pipeline_wait_prior(0);
        }
        __syncthreads();

        const float* As = Asb + buf * ASZ;
        const float* Bs = Bsb + buf * BSZ;
#pragma unroll
        for (int k8 = 0; k8 < 2; k8++) {
            const int kb = k8 * 8;
            float2 a[MI][4];
#pragma unroll
            for (int i = 0; i < MI; i++) {
                int ml = wm * WarpM + i * 16 + lr;
                a[i][0] = *(const float2*)(As + ml * 40 + (kb + lc) * 2);
                a[i][1] = *(const float2*)(As + (ml + 8) * 40 + (kb + lc) * 2);
                a[i][2] = *(const float2*)(As + ml * 40 + (kb + lc + 4) * 2);
                a[i][3] = *(const float2*)(As + (ml + 8) * 40 + (kb + lc + 4) * 2);
            }
#pragma unroll
            for (int j = 0; j < NJ; j++) {
                int nl = wn * WarpN + j * 8 + lr;
                float2 b0 = *(const float2*)(Bs + nl * 40 + (kb + lc) * 2);
                float2 b1 = *(const float2*)(Bs + nl * 40 + (kb + lc + 4) * 2);
#pragma unroll
                for (int i = 0; i < MI; i++) {
                    uint32_t ah0 = __float_as_uint(a[i][0].x), ah1 = __float_as_uint(a[i][1].x);
                    uint32_t ah2 = __float_as_uint(a[i][2].x), ah3 = __float_as_uint(a[i][3].x);
                    uint32_t al0 = __float_as_uint(a[i][0].y), al1 = __float_as_uint(a[i][1].y);
                    uint32_t al2 = __float_as_uint(a[i][2].y), al3 = __float_as_uint(a[i][3].y);
                    uint32_t bh0 = __float_as_uint(b0.x), bh1 = __float_as_uint(b1.x);
                    uint32_t bl0 = __float_as_uint(b0.y), bl1 = __float_as_uint(b1.y);
                    mma_tf32(C[i][j], ah0, ah1, ah2, ah3, bh0, bh1);   // hi*hi
                    mma_tf32(C[i][j], al0, al1, al2, al3, bh0, bh1);   // lo*hi
                    mma_tf32(C[i][j], ah0, ah1, ah2, ah3, bl0, bl1);   // hi*lo
                }
            }
        }

        if (more) {
            // split + store A tile t+1 into the alternate buffer
            float* An = Asb + nbuf * ASZ;
#pragma unroll
            for (int it = 0; it < 2; it++) {
                int lin = tid + it * 256;
                int m = lin >> 2, kq = lin & 3;
                float2 s0 = split_tf32(xv[it].x), s1 = split_tf32(xv[it].y);
                float2 s2 = split_tf32(xv[it].z), s3 = split_tf32(xv[it].w);
                float* p = An + m * 40 + kq * 8;
                *(float4*)p       = make_float4(s0.x, s0.y, s1.x, s1.y);
                *(float4*)(p + 4) = make_float4(s2.x, s2.y, s3.x, s3.y);
            }
        }
        __syncthreads();
    }

    // ---- store ----
#pragma unroll
    for (int i = 0; i < MI; i++) {
        int r0 = m0 + wm * WarpM + i * 16 + lr;
#pragma unroll
        for (int j = 0; j < NJ; j++) {
            int col = wn * WarpN + j * 8 + lc * 2;
            if (r0 < M)
                *(float2*)(Y + (size_t)r0 * N + col) = make_float2(C[i][j].x, C[i][j].y);
            if (r0 + 8 < M)
                *(float2*)(Y + (size_t)(r0 + 8) * N + col) = make_float2(C[i][j].z, C[i][j].w);
        }
    }
}

// ---------------------------------------------------------------------------
// Fused dual gather (multi-edge-per-warp, LDG.128)
// ---------------------------------------------------------------------------
struct GatherCfg {
    const float* tmA; const int* csrA; const int* rsA;
    const float* tmB; const int* csrB; const int* rsB;
    const float* bias; float* out;
};

template<int D, int LD, bool RELU>
__launch_bounds__(256)
__global__ void gather_dual_kernel(GatherCfg c0, GatherCfg c1, int n) {
    constexpr int LANES  = D / 4;
    constexpr int GROUPS = 32 / LANES;
    const GatherCfg c = blockIdx.y ? c1 : c0;
    int warp = (blockIdx.x * blockDim.x + threadIdx.x) >> 5;
    int lane = threadIdx.x & 31;
    if (warp >= n) return;
    int grp = lane / LANES;
    int h   = lane % LANES;

    float4 res = *(const float4*)(c.bias + h * 4);

#pragma unroll
    for (int rel = 0; rel < 2; rel++) {
        const float* __restrict__ tm  = rel ? c.tmB  : c.tmA;
        const int*   __restrict__ csr = rel ? c.csrB : c.csrA;
        const int*   __restrict__ rs  = rel ? c.rsB  : c.rsA;
        int s = rs[warp], e = rs[warp + 1];
        float inv = 1.0f / (float)max(e - s, 1);
        float4 acc = make_float4(0.f, 0.f, 0.f, 0.f);
        int i = s + grp;
        for (; i + GROUPS < e; i += 2 * GROUPS) {
            int r0 = csr[i];
            int r1 = csr[i + GROUPS];
            float4 v0 = *(const float4*)(tm + (size_t)r0 * LD + h * 4);
            float4 v1 = *(const float4*)(tm + (size_t)r1 * LD + h * 4);
            acc.x += v0.x + v1.x; acc.y += v0.y + v1.y;
            acc.z += v0.z + v1.z; acc.w += v0.w + v1.w;
        }
        if (i < e) {
            int r0 = csr[i];
            float4 v0 = *(const float4*)(tm + (size_t)r0 * LD + h * 4);
            acc.x += v0.x; acc.y += v0.y; acc.z += v0.z; acc.w += v0.w;
        }
#pragma unroll
        for (int off = LANES; off < 32; off <<= 1) {
            acc.x += __shfl_xor_sync(~0u, acc.x, off);
            acc.y += __shfl_xor_sync(~0u, acc.y, off);
            acc.z += __shfl_xor_sync(~0u, acc.z, off);
            acc.w += __shfl_xor_sync(~0u, acc.w, off);
        }
        res.x += acc.x * inv; res.y += acc.y * inv;
        res.z += acc.z * inv; res.w += acc.w * inv;
    }

    if (RELU) {
        res.x = fmaxf(res.x, 0.f); res.y = fmaxf(res.y, 0.f);
        res.z = fmaxf(res.z, 0.f); res.w = fmaxf(res.w, 0.f);
    }
    if (grp == 0)
        ((float4*)(c.out + (size_t)warp * D))[h] = res;
}

// ---------------------------------------------------------------------------
// Orchestration
// ---------------------------------------------------------------------------
extern "C" void kernel_launch(void* const* d_in, const int* in_sizes, int n_in,
                              void* d_out, int out_size) {
    const float* xd = (const float*)d_in[0];
    const float* xg = (const float*)d_in[1];
    const int* es[8];
    for (int i = 0; i < 8; i++) es[i] = (const int*)d_in[2 + i];
    const float* W1[4] = {(const float*)d_in[10], (const float*)d_in[11],
                          (const float*)d_in[12], (const float*)d_in[13]};
    const float* b1d = (const float*)d_in[14];
    const float* b1g = (const float*)d_in[15];
    const float* W2[4] = {(const float*)d_in[16], (const float*)d_in[17],
                          (const float*)d_in[18], (const float*)d_in[19]};
    const float* b2d = (const float*)d_in[20];
    const float* b2g = (const float*)d_in[21];
    float* out = (float*)d_out;
    const int E = in_sizes[2];

    float *tm, *h, *wt1, *wt2;
    int *deg, *rowstart, *cursor, *csr;
    cudaGetSymbolAddress((void**)&tm,       g_tm);
    cudaGetSymbolAddress((void**)&h,        g_h);
    cudaGetSymbolAddress((void**)&wt1,      g_wt1);
    cudaGetSymbolAddress((void**)&wt2,      g_wt2);
    cudaGetSymbolAddress((void**)&deg,      g_deg);
    cudaGetSymbolAddress((void**)&rowstart, g_rowstart);
    cudaGetSymbolAddress((void**)&cursor,   g_cursor);
    cudaGetSymbolAddress((void**)&csr,      g_csr);

    const int TB = 256;
    const int gblk = (NDRUG + 127) / 128;                 // 391
    const int eblk4 = (E + TB * 4 - 1) / (TB * 4);
    const int estride = eblk4 * TB;

    // dynamic smem sizes: (2*128*40 + 2*N*40) * 4 bytes
    const int smem1 = (2 * 128 * 40 + 2 * 128 * 40) * 4;  // 81920
    const int smem2 = (2 * 128 * 40 + 2 * 64 * 40) * 4;   // 61440
    cudaFuncSetAttribute((const void*)gemmt_kernel<128, 128, 4>,
                         cudaFuncAttributeMaxDynamicSharedMemorySize, smem1);
    cudaFuncSetAttribute((const void*)gemmt_kernel<64, 64, 8>,
                         cudaFuncAttributeMaxDynamicSharedMemorySize, smem2);

    Iptr4 srcs = {{es[0], es[2], es[4], es[6]}};
    Iptr4 dsts = {{es[1], es[3], es[5], es[7]}};

    float* tm0 = tm;
    float* tm1 = tm + (size_t)NDRUG * 128;
    float* wt1d = wt1;                 float* wt1g = wt1 + 8 * 128 * 40;
    float* wt2d = wt2;                 float* wt2g = wt2 + 4 * 64 * 40;

    // --- prep: degrees + tf32 split-pack of weights ---
    cudaMemsetAsync(deg, 0, sizeof(int) * 4 * NDRUG, 0);
    PackAll pa;
    for (int i = 0; i < 4; i++) { pa.w1[i] = W1[i]; pa.w2[i] = W2[i]; }
    pa.wt1d = wt1d; pa.wt1g = wt1g; pa.wt2d = wt2d; pa.wt2g = wt2g;
    prep_kernel<<<dim3(eblk4, 5), TB>>>(dsts, deg, E, estride, pa);

    // --- scan (writes rowstart + cursor) ---
    scan4_kernel<<<4, 1024>>>(deg, rowstart, cursor);

    // --- CSR fill ---
    fill4_kernel<<<dim3(eblk4, 4), TB>>>(srcs, dsts, cursor, csr, E, estride);

    const int* rs[4] = {rowstart, rowstart + (NDRUG + 1),
                        rowstart + 2 * (NDRUG + 1), rowstart + 3 * (NDRUG + 1)};
    const int* cs[4] = {csr, csr + EMAX, csr + 2 * (size_t)EMAX, csr + 3 * (size_t)EMAX};

    int gather_blocks = (NDRUG * 32 + TB - 1) / TB;

    // --- layer 1: pipelined tf32 tensor GEMM + fused gather ---
    {
        Ptr2  X = {{xd, xg}};
        Ptr2  W = {{wt1d, wt1g}};
        Fptr2 Y = {{tm0, tm1}};
        gemmt_kernel<128, 128, 4><<<dim3(gblk, 2), 256, smem1>>>(X, W, Y, NDRUG);

        GatherCfg cd = {tm0,      cs[0], rs[0], tm1,      cs[2], rs[2], b1d, h};
        GatherCfg cg = {tm0 + 64, cs[1], rs[1], tm1 + 64, cs[3], rs[3], b1g,
                        h + (size_t)NDRUG * DHID};
        gather_dual_kernel<64, 128, true><<<dim3(gather_blocks, 2), TB>>>(cd, cg, NDRUG);
    }

    // --- layer 2 ---
    {
        const float* hd = h;
        const float* hg = h + (size_t)NDRUG * DHID;
        Ptr2  X = {{hd, hg}};
        Ptr2  W = {{wt2d, wt2g}};
        Fptr2 Y = {{tm0, tm1}};
        gemmt_kernel<64, 64, 8><<<dim3(gblk, 2), 256, smem2>>>(X, W, Y, NDRUG);

        GatherCfg cd = {tm0,      cs[0], rs[0], tm1,      cs[2], rs[2], b2d, out};
        GatherCfg cg = {tm0 + 32, cs[1], rs[1], tm1 + 32, cs[3], rs[3], b2g,
                        out + (size_t)NDRUG * DEMB};
        gather_dual_kernel<32, 64, false><<<dim3(gather_blocks, 2), TB>>>(cd, cg, NDRUG);
    }
}

// round 15
// speedup vs baseline: 1.3468x; 1.2061x over previous
#include <cuda_runtime.h>
#include <cuda_pipeline.h>
#include <cstdint>

constexpr int NDRUG = 50000;
constexpr int NGENE = 50000;
constexpr int DHID  = 64;
constexpr int DEMB  = 32;
constexpr int EMAX  = 600000;

// Scratch (device globals — no allocation allowed)
__device__ float g_tm[2][NDRUG * 128];
__device__ float g_h[2][NDRUG * DHID];
__device__ float g_wt1[2][8 * 128 * 40];   // layer-1 weights, tf32 hi/lo split, tile-major
__device__ float g_wt2[2][4 * 64 * 40];    // layer-2 weights, split
__device__ int   g_deg[4 * NDRUG];
__device__ int   g_rowstart[4 * (NDRUG + 1)];
__device__ int   g_cursor[4 * (NDRUG + 1)];
__device__ int   g_csr[4 * EMAX];

struct Iptr4 { const int* p[4]; };
struct Ptr2  { const float* p[2]; };
struct Fptr2 { float* p[2]; };
struct PackAll {
    const float* w1[4];
    const float* w2[4];
    float *wt1d, *wt1g, *wt2d, *wt2g;
};

// ---------------------------------------------------------------------------
// tf32 helpers
// ---------------------------------------------------------------------------
__device__ __forceinline__ float2 split_tf32(float v) {
    uint32_t hb;
    asm("cvt.rna.tf32.f32 %0, %1;" : "=r"(hb) : "f"(v));
    float hi = __uint_as_float(hb);
    float lo = v - hi;
    uint32_t lb;
    asm("cvt.rna.tf32.f32 %0, %1;" : "=r"(lb) : "f"(lo));
    return make_float2(hi, __uint_as_float(lb));
}

__device__ __forceinline__ void mma_tf32(float4& c, uint32_t a0, uint32_t a1,
                                         uint32_t a2, uint32_t a3,
                                         uint32_t b0, uint32_t b1) {
    asm volatile(
        "mma.sync.aligned.m16n8k8.row.col.f32.tf32.tf32.f32 "
        "{%0,%1,%2,%3}, {%4,%5,%6,%7}, {%8,%9}, {%0,%1,%2,%3};"
        : "+f"(c.x), "+f"(c.y), "+f"(c.z), "+f"(c.w)
        : "r"(a0), "r"(a1), "r"(a2), "r"(a3), "r"(b0), "r"(b1));
}

// ---------------------------------------------------------------------------
// degree histogram (side stream), 4 edges/thread
// ---------------------------------------------------------------------------
__global__ void degree4_kernel(Iptr4 dst, int* __restrict__ deg, int E, int stride) {
    int y = blockIdx.y;
    int idx = blockIdx.x * blockDim.x + threadIdx.x;
    const int* d = dst.p[y];
    int* dg = deg + y * NDRUG;
    int i0 = idx, i1 = idx + stride, i2 = idx + 2 * stride, i3 = idx + 3 * stride;
    if (i0 < E) atomicAdd(&dg[d[i0]], 1);
    if (i1 < E) atomicAdd(&dg[d[i1]], 1);
    if (i2 < E) atomicAdd(&dg[d[i2]], 1);
    if (i3 < E) atomicAdd(&dg[d[i3]], 1);
}

// ---------------------------------------------------------------------------
// weight split-pack (main stream, feeds gemm1 immediately)
// ---------------------------------------------------------------------------
__global__ void pack_kernel(PackAll pa) {
    int idx = blockIdx.x * blockDim.x + threadIdx.x;
    if (idx < 32768) {                       // layer 1: 2 src x 128 k x 128 n
        int src = idx >> 14;
        int j   = idx & 16383;
        int kg  = j >> 7;
        int n   = j & 127;
        float v = (n < 64) ? pa.w1[src * 2][kg * 64 + n]
                           : pa.w1[src * 2 + 1][kg * 64 + n - 64];
        float2 s = split_tf32(v);
        float* dstp = (src ? pa.wt1g : pa.wt1d)
                    + (size_t)(kg / 16) * 128 * 40 + n * 40 + (kg % 16) * 2;
        dstp[0] = s.x; dstp[1] = s.y;
    } else if (idx < 40960) {                // layer 2: 2 src x 64 k x 64 n
        int j   = idx - 32768;
        int src = j >> 12;
        int jj  = j & 4095;
        int kg  = jj >> 6;
        int n   = jj & 63;
        float v = (n < 32) ? pa.w2[src * 2][kg * 32 + n]
                           : pa.w2[src * 2 + 1][kg * 32 + n - 32];
        float2 s = split_tf32(v);
        float* dstp = (src ? pa.wt2g : pa.wt2d)
                    + (size_t)(kg / 16) * 64 * 40 + n * 40 + (kg % 16) * 2;
        dstp[0] = s.x; dstp[1] = s.y;
    }
}

// ---------------------------------------------------------------------------
// exclusive prefix scan of degrees -> rowstart AND cursor; 1 block/relation
// ---------------------------------------------------------------------------
__global__ __launch_bounds__(1024)
void scan4_kernel(const int* __restrict__ deg, int* __restrict__ rowstart,
                  int* __restrict__ cursor) {
    int r = blockIdx.x;
    const int* dg = deg + r * NDRUG;
    int* rs = rowstart + (size_t)r * (NDRUG + 1);
    int* cu = cursor   + (size_t)r * (NDRUG + 1);
    __shared__ int warpsum[32];
    __shared__ int carry_sh;
    int t = threadIdx.x, lane = t & 31, w = t >> 5;
    if (t == 0) carry_sh = 0;
    __syncthreads();
    for (int base = 0; base < NDRUG; base += 1024) {
        int idx = base + t;
        int v = (idx < NDRUG) ? dg[idx] : 0;
        int x = v;
#pragma unroll
        for (int off = 1; off < 32; off <<= 1) {
            int yv = __shfl_up_sync(~0u, x, off);
            if (lane >= off) x += yv;
        }
        if (lane == 31) warpsum[w] = x;
        __syncthreads();
        if (w == 0) {
            int s = warpsum[lane];
#pragma unroll
            for (int off = 1; off < 32; off <<= 1) {
                int yv = __shfl_up_sync(~0u, s, off);
                if (lane >= off) s += yv;
            }
            warpsum[lane] = s;
        }
        __syncthreads();
        int woff = (w > 0) ? warpsum[w - 1] : 0;
        int incl = x + woff;
        int carry = carry_sh;
        if (idx < NDRUG) { int val = carry + incl - v; rs[idx] = val; cu[idx] = val; }
        __syncthreads();
        if (t == 1023) carry_sh = carry + incl;
        __syncthreads();
    }
    if (t == 0) { rs[NDRUG] = carry_sh; cu[NDRUG] = carry_sh; }
}

// ---------------------------------------------------------------------------
// CSR fill: 4 independent edges per thread
// ---------------------------------------------------------------------------
__global__ void fill4_kernel(Iptr4 src, Iptr4 dst, int* __restrict__ cursor,
                             int* __restrict__ csr, int E, int stride) {
    int r = blockIdx.y;
    const int* s = src.p[r];
    const int* d = dst.p[r];
    int* cu = cursor + (size_t)r * (NDRUG + 1);
    int* cs = csr + (size_t)r * EMAX;
    int idx = blockIdx.x * blockDim.x + threadIdx.x;
    int i0 = idx, i1 = idx + stride, i2 = idx + 2 * stride, i3 = idx + 3 * stride;
    int d0 = (i0 < E) ? d[i0] : 0;
    int d1 = (i1 < E) ? d[i1] : 0;
    int d2 = (i2 < E) ? d[i2] : 0;
    int d3 = (i3 < E) ? d[i3] : 0;
    int p0 = (i0 < E) ? atomicAdd(&cu[d0], 1) : 0;
    int p1 = (i1 < E) ? atomicAdd(&cu[d1], 1) : 0;
    int p2 = (i2 < E) ? atomicAdd(&cu[d2], 1) : 0;
    int p3 = (i3 < E) ? atomicAdd(&cu[d3], 1) : 0;
    if (i0 < E) cs[p0] = s[i0];
    if (i1 < E) cs[p1] = s[i1];
    if (i2 < E) cs[p2] = s[i2];
    if (i3 < E) cs[p3] = s[i3];
}

// ---------------------------------------------------------------------------
// Pipelined TF32 tensor-core GEMM (3xTF32): Y[y][M,N] = X[y][M,K] @ W[y][K,N]
// Double-buffered dynamic smem; B via cp.async; A via register prefetch.
// ---------------------------------------------------------------------------
template<int K, int N, int MW>
__global__ __launch_bounds__(256, 2)
void gemmt_kernel(Ptr2 Xa, Ptr2 Wta, Fptr2 Ya, int M) {
    constexpr int NW    = 8 / MW;
    constexpr int WarpM = 128 / MW;
    constexpr int WarpN = N / NW;
    constexpr int MI    = WarpM / 16;
    constexpr int NJ    = WarpN / 8;
    constexpr int NT    = K / 16;
    constexpr int ASZ   = 128 * 40;
    constexpr int BSZ   = N * 40;

    const int y = blockIdx.y;
    const float* __restrict__ X  = Xa.p[y];
    const float* __restrict__ Wt = Wta.p[y];
    float* __restrict__ Y = Ya.p[y];

    extern __shared__ float sm[];
    float* Asb = sm;
    float* Bsb = sm + 2 * ASZ;

    const int tid  = threadIdx.x;
    const int warp = tid >> 5, lane = tid & 31;
    const int wm = warp % MW, wn = warp / MW;
    const int m0 = blockIdx.x * 128;
    const int lr = lane >> 2;
    const int lc = lane & 3;

    float4 C[MI][NJ];
#pragma unroll
    for (int i = 0; i < MI; i++)
#pragma unroll
        for (int j = 0; j < NJ; j++) C[i][j] = make_float4(0.f, 0.f, 0.f, 0.f);

    float4 xv[2];

    // ---- prologue: tile 0 ----
#pragma unroll
    for (int it = 0; it < 2; it++) {
        int lin = tid + it * 256;
        int m = lin >> 2, kq = lin & 3;
        int gr = m0 + m;
        xv[it] = make_float4(0.f, 0.f, 0.f, 0.f);
        if (gr < M) xv[it] = *(const float4*)(X + (size_t)gr * K + kq * 4);
    }
#pragma unroll
    for (int it = 0; it < 2; it++) {
        int lin = tid + it * 256;
        int m = lin >> 2, kq = lin & 3;
        float2 s0 = split_tf32(xv[it].x), s1 = split_tf32(xv[it].y);
        float2 s2 = split_tf32(xv[it].z), s3 = split_tf32(xv[it].w);
        float* p = Asb + m * 40 + kq * 8;
        *(float4*)p       = make_float4(s0.x, s0.y, s1.x, s1.y);
        *(float4*)(p + 4) = make_float4(s2.x, s2.y, s3.x, s3.y);
    }
    {
        const float4* src = (const float4*)Wt;
        float4* dst = (float4*)Bsb;
        for (int i = tid; i < BSZ / 4; i += 256)
            __pipeline_memcpy_async(dst + i, src + i, 16);
    }
    __pipeline_commit();

    for (int t = 0; t < NT; t++) {
        const int buf  = t & 1;
        const int nbuf = buf ^ 1;
        const bool more = (t + 1 < NT);

        if (more) {
#pragma unroll
            for (int it = 0; it < 2; it++) {
                int lin = tid + it * 256;
                int m = lin >> 2, kq = lin & 3;
                int gr = m0 + m;
                xv[it] = make_float4(0.f, 0.f, 0.f, 0.f);
                if (gr < M)
                    xv[it] = *(const float4*)(X + (size_t)gr * K + (t + 1) * 16 + kq * 4);
            }
            const float4* src = (const float4*)(Wt + (size_t)(t + 1) * BSZ);
            float4* dst = (float4*)(Bsb + nbuf * BSZ);
            for (int i = tid; i < BSZ / 4; i += 256)
                __pipeline_memcpy_async(dst + i, src + i, 16);
            __pipeline_commit();
            __pipeline_wait_prior(1);
        } else {
            __pipeline_wait_prior(0);
        }
        __syncthreads();

        const float* As = Asb + buf * ASZ;
        const float* Bs = Bsb + buf * BSZ;
#pragma unroll
        for (int k8 = 0; k8 < 2; k8++) {
            const int kb = k8 * 8;
            float2 a[MI][4];
#pragma unroll
            for (int i = 0; i < MI; i++) {
                int ml = wm * WarpM + i * 16 + lr;
                a[i][0] = *(const float2*)(As + ml * 40 + (kb + lc) * 2);
                a[i][1] = *(const float2*)(As + (ml + 8) * 40 + (kb + lc) * 2);
                a[i][2] = *(const float2*)(As + ml * 40 + (kb + lc + 4) * 2);
                a[i][3] = *(const float2*)(As + (ml + 8) * 40 + (kb + lc + 4) * 2);
            }
#pragma unroll
            for (int j = 0; j < NJ; j++) {
                int nl = wn * WarpN + j * 8 + lr;
                float2 b0 = *(const float2*)(Bs + nl * 40 + (kb + lc) * 2);
                float2 b1 = *(const float2*)(Bs + nl * 40 + (kb + lc + 4) * 2);
#pragma unroll
                for (int i = 0; i < MI; i++) {
                    uint32_t ah0 = __float_as_uint(a[i][0].x), ah1 = __float_as_uint(a[i][1].x);
                    uint32_t ah2 = __float_as_uint(a[i][2].x), ah3 = __float_as_uint(a[i][3].x);
                    uint32_t al0 = __float_as_uint(a[i][0].y), al1 = __float_as_uint(a[i][1].y);
                    uint32_t al2 = __float_as_uint(a[i][2].y), al3 = __float_as_uint(a[i][3].y);
                    uint32_t bh0 = __float_as_uint(b0.x), bh1 = __float_as_uint(b1.x);
                    uint32_t bl0 = __float_as_uint(b0.y), bl1 = __float_as_uint(b1.y);
                    mma_tf32(C[i][j], ah0, ah1, ah2, ah3, bh0, bh1);   // hi*hi
                    mma_tf32(C[i][j], al0, al1, al2, al3, bh0, bh1);   // lo*hi
                    mma_tf32(C[i][j], ah0, ah1, ah2, ah3, bl0, bl1);   // hi*lo
                }
            }
        }

        if (more) {
            float* An = Asb + nbuf * ASZ;
#pragma unroll
            for (int it = 0; it < 2; it++) {
                int lin = tid + it * 256;
                int m = lin >> 2, kq = lin & 3;
                float2 s0 = split_tf32(xv[it].x), s1 = split_tf32(xv[it].y);
                float2 s2 = split_tf32(xv[it].z), s3 = split_tf32(xv[it].w);
                float* p = An + m * 40 + kq * 8;
                *(float4*)p       = make_float4(s0.x, s0.y, s1.x, s1.y);
                *(float4*)(p + 4) = make_float4(s2.x, s2.y, s3.x, s3.y);
            }
        }
        __syncthreads();
    }

    // ---- store ----
#pragma unroll
    for (int i = 0; i < MI; i++) {
        int r0 = m0 + wm * WarpM + i * 16 + lr;
#pragma unroll
        for (int j = 0; j < NJ; j++) {
            int col = wn * WarpN + j * 8 + lc * 2;
            if (r0 < M)
                *(float2*)(Y + (size_t)r0 * N + col) = make_float2(C[i][j].x, C[i][j].y);
            if (r0 + 8 < M)
                *(float2*)(Y + (size_t)(r0 + 8) * N + col) = make_float2(C[i][j].z, C[i][j].w);
        }
    }
}

// ---------------------------------------------------------------------------
// Fused dual gather (multi-edge-per-warp, LDG.128)
// ---------------------------------------------------------------------------
struct GatherCfg {
    const float* tmA; const int* csrA; const int* rsA;
    const float* tmB; const int* csrB; const int* rsB;
    const float* bias; float* out;
};

template<int D, int LD, bool RELU>
__launch_bounds__(256)
__global__ void gather_dual_kernel(GatherCfg c0, GatherCfg c1, int n) {
    constexpr int LANES  = D / 4;
    constexpr int GROUPS = 32 / LANES;
    const GatherCfg c = blockIdx.y ? c1 : c0;
    int warp = (blockIdx.x * blockDim.x + threadIdx.x) >> 5;
    int lane = threadIdx.x & 31;
    if (warp >= n) return;
    int grp = lane / LANES;
    int h   = lane % LANES;

    float4 res = *(const float4*)(c.bias + h * 4);

#pragma unroll
    for (int rel = 0; rel < 2; rel++) {
        const float* __restrict__ tm  = rel ? c.tmB  : c.tmA;
        const int*   __restrict__ csr = rel ? c.csrB : c.csrA;
        const int*   __restrict__ rs  = rel ? c.rsB  : c.rsA;
        int s = rs[warp], e = rs[warp + 1];
        float inv = 1.0f / (float)max(e - s, 1);
        float4 acc = make_float4(0.f, 0.f, 0.f, 0.f);
        int i = s + grp;
        for (; i + GROUPS < e; i += 2 * GROUPS) {
            int r0 = csr[i];
            int r1 = csr[i + GROUPS];
            float4 v0 = *(const float4*)(tm + (size_t)r0 * LD + h * 4);
            float4 v1 = *(const float4*)(tm + (size_t)r1 * LD + h * 4);
            acc.x += v0.x + v1.x; acc.y += v0.y + v1.y;
            acc.z += v0.z + v1.z; acc.w += v0.w + v1.w;
        }
        if (i < e) {
            int r0 = csr[i];
            float4 v0 = *(const float4*)(tm + (size_t)r0 * LD + h * 4);
            acc.x += v0.x; acc.y += v0.y; acc.z += v0.z; acc.w += v0.w;
        }
#pragma unroll
        for (int off = LANES; off < 32; off <<= 1) {
            acc.x += __shfl_xor_sync(~0u, acc.x, off);
            acc.y += __shfl_xor_sync(~0u, acc.y, off);
            acc.z += __shfl_xor_sync(~0u, acc.z, off);
            acc.w += __shfl_xor_sync(~0u, acc.w, off);
        }
        res.x += acc.x * inv; res.y += acc.y * inv;
        res.z += acc.z * inv; res.w += acc.w * inv;
    }

    if (RELU) {
        res.x = fmaxf(res.x, 0.f); res.y = fmaxf(res.y, 0.f);
        res.z = fmaxf(res.z, 0.f); res.w = fmaxf(res.w, 0.f);
    }
    if (grp == 0)
        ((float4*)(c.out + (size_t)warp * D))[h] = res;
}

// ---------------------------------------------------------------------------
// Orchestration — two-branch capture graph:
//   side:  memset(deg) -> degree -> scan -> fill      (CSR build)
//   main:  pack -> gemm1                               (transform)
//   join -> gather1 -> gemm2 -> gather2
// ---------------------------------------------------------------------------
extern "C" void kernel_launch(void* const* d_in, const int* in_sizes, int n_in,
                              void* d_out, int out_size) {
    const float* xd = (const float*)d_in[0];
    const float* xg = (const float*)d_in[1];
    const int* es[8];
    for (int i = 0; i < 8; i++) es[i] = (const int*)d_in[2 + i];
    const float* W1[4] = {(const float*)d_in[10], (const float*)d_in[11],
                          (const float*)d_in[12], (const float*)d_in[13]};
    const float* b1d = (const float*)d_in[14];
    const float* b1g = (const float*)d_in[15];
    const float* W2[4] = {(const float*)d_in[16], (const float*)d_in[17],
                          (const float*)d_in[18], (const float*)d_in[19]};
    const float* b2d = (const float*)d_in[20];
    const float* b2g = (const float*)d_in[21];
    float* out = (float*)d_out;
    const int E = in_sizes[2];

    float *tm, *h, *wt1, *wt2;
    int *deg, *rowstart, *cursor, *csr;
    cudaGetSymbolAddress((void**)&tm,       g_tm);
    cudaGetSymbolAddress((void**)&h,        g_h);
    cudaGetSymbolAddress((void**)&wt1,      g_wt1);
    cudaGetSymbolAddress((void**)&wt2,      g_wt2);
    cudaGetSymbolAddress((void**)&deg,      g_deg);
    cudaGetSymbolAddress((void**)&rowstart, g_rowstart);
    cudaGetSymbolAddress((void**)&cursor,   g_cursor);
    cudaGetSymbolAddress((void**)&csr,      g_csr);

    const int TB = 256;
    const int gblk = (NDRUG + 127) / 128;
    const int eblk4 = (E + TB * 4 - 1) / (TB * 4);
    const int estride = eblk4 * TB;

    const int smem1 = (2 * 128 * 40 + 2 * 128 * 40) * 4;  // 81920
    const int smem2 = (2 * 128 * 40 + 2 * 64 * 40) * 4;   // 61440
    cudaFuncSetAttribute((const void*)gemmt_kernel<128, 128, 4>,
                         cudaFuncAttributeMaxDynamicSharedMemorySize, smem1);
    cudaFuncSetAttribute((const void*)gemmt_kernel<64, 64, 8>,
                         cudaFuncAttributeMaxDynamicSharedMemorySize, smem2);

    // side stream + fork/join events (created once, outside any capture;
    // host-side objects only — no device memory)
    static cudaStream_t s_side = nullptr;
    static cudaEvent_t  s_evF  = nullptr;
    static cudaEvent_t  s_evJ  = nullptr;
    if (s_side == nullptr) {
        cudaStreamCreateWithFlags(&s_side, cudaStreamNonBlocking);
        cudaEventCreateWithFlags(&s_evF, cudaEventDisableTiming);
        cudaEventCreateWithFlags(&s_evJ, cudaEventDisableTiming);
    }

    Iptr4 srcs = {{es[0], es[2], es[4], es[6]}};
    Iptr4 dsts = {{es[1], es[3], es[5], es[7]}};

    float* tm0 = tm;
    float* tm1 = tm + (size_t)NDRUG * 128;
    float* wt1d = wt1;                 float* wt1g = wt1 + 8 * 128 * 40;
    float* wt2d = wt2;                 float* wt2g = wt2 + 4 * 64 * 40;

    const int* rs[4] = {rowstart, rowstart + (NDRUG + 1),
                        rowstart + 2 * (NDRUG + 1), rowstart + 3 * (NDRUG + 1)};
    const int* cs[4] = {csr, csr + EMAX, csr + 2 * (size_t)EMAX, csr + 3 * (size_t)EMAX};

    // ---- fork: CSR build on side stream ----
    cudaEventRecord(s_evF, 0);
    cudaStreamWaitEvent(s_side, s_evF, 0);
    cudaMemsetAsync(deg, 0, sizeof(int) * 4 * NDRUG, s_side);
    degree4_kernel<<<dim3(eblk4, 4), TB, 0, s_side>>>(dsts, deg, E, estride);
    scan4_kernel<<<4, 1024, 0, s_side>>>(deg, rowstart, cursor);
    fill4_kernel<<<dim3(eblk4, 4), TB, 0, s_side>>>(srcs, dsts, cursor, csr, E, estride);
    cudaEventRecord(s_evJ, s_side);

    // ---- main: pack -> gemm1 ----
    PackAll pa;
    for (int i = 0; i < 4; i++) { pa.w1[i] = W1[i]; pa.w2[i] = W2[i]; }
    pa.wt1d = wt1d; pa.wt1g = wt1g; pa.wt2d = wt2d; pa.wt2g = wt2g;
    pack_kernel<<<160, TB>>>(pa);

    {
        Ptr2  X = {{xd, xg}};
        Ptr2  W = {{wt1d, wt1g}};
        Fptr2 Y = {{tm0, tm1}};
        gemmt_kernel<128, 128, 4><<<dim3(gblk, 2), 256, smem1>>>(X, W, Y, NDRUG);
    }

    // ---- join: CSR branch must be complete before gather1 ----
    cudaStreamWaitEvent(0, s_evJ, 0);

    int gather_blocks = (NDRUG * 32 + TB - 1) / TB;

    // ---- gather1 ----
    {
        GatherCfg cd = {tm0,      cs[0], rs[0], tm1,      cs[2], rs[2], b1d, h};
        GatherCfg cg = {tm0 + 64, cs[1], rs[1], tm1 + 64, cs[3], rs[3], b1g,
                        h + (size_t)NDRUG * DHID};
        gather_dual_kernel<64, 128, true><<<dim3(gather_blocks, 2), TB>>>(cd, cg, NDRUG);
    }

    // ---- layer 2 ----
    {
        const float* hd = h;
        const float* hg = h + (size_t)NDRUG * DHID;
        Ptr2  X = {{hd, hg}};
        Ptr2  W = {{wt2d, wt2g}};
        Fptr2 Y = {{tm0, tm1}};
        gemmt_kernel<64, 64, 8><<<dim3(gblk, 2), 256, smem2>>>(X, W, Y, NDRUG);

        GatherCfg cd = {tm0,      cs[0], rs[0], tm1,      cs[2], rs[2], b2d, out};
        GatherCfg cg = {tm0 + 32, cs[1], rs[1], tm1 + 32, cs[3], rs[3], b2g,
                        out + (size_t)NDRUG * DEMB};
        gather_dual_kernel<32, 64, false><<<dim3(gather_blocks, 2), TB>>>(cd, cg, NDRUG);
    }
}